// round 8
// baseline (speedup 1.0000x reference)
#include <cuda_runtime.h>
#include <cuda_fp16.h>
#include <cuda_bf16.h>

#define NNODES 100000
#define NEDGES 1600000
#define INF    128
#define HF     64     // HEADS*OUT_FEATS
#define NEG_SLOPE 0.2f
#define EPS_F  1e-16f

#define GB_NODES 256                         // nodes per gemm block
#define NGB ((NNODES + GB_NODES - 1) / GB_NODES)   // 391 gemm blocks
#define SBLK 256
#define NSB  ((NNODES + SBLK - 1) / SBLK)    // 391 scan blocks

typedef unsigned long long u64;

// ---------------- static device scratch (no allocations allowed) ----------
// State-recycling invariant: g_counts and g_state are all-zero on entry to
// every kernel_launch call (BSS-zero initially; scan re-zeroes counts after
// consuming them, scatter re-zeroes the lookback states after scan).
__device__ __half g_hh[NNODES * HF];         // 12.8 MB projected features (fp16)
__device__ float4 g_el[NNODES];              // [N][4] left scores
__device__ float4 g_er[NNODES];              // [N][4] right scores
__device__ int    g_counts[NNODES];
__device__ int    g_cursor[NNODES];
__device__ int    g_rowptr[NNODES + 1];
__device__ int    g_psrc[NEDGES];            // src ids grouped by target
__device__ u64    g_state[NSB];              // lookback: (sum<<2)|{0,1,2}

// ---------------- packed f32x2 helpers (sm_103a FFMA2) --------------------
__device__ __forceinline__ u64 ffma2(u64 a, u64 b, u64 c) {
    u64 d;
    asm("fma.rn.f32x2 %0, %1, %2, %3;" : "=l"(d) : "l"(a), "l"(b), "l"(c));
    return d;
}
__device__ __forceinline__ u64 bcast2(float x) {
    u64 d;
    unsigned u = __float_as_uint(x);
    asm("mov.b64 %0, {%1, %1};" : "=l"(d) : "r"(u));
    return d;
}
__device__ __forceinline__ void unpack2(u64 v, float& lo, float& hi) {
    unsigned a, b;
    asm("mov.b64 {%0, %1}, %2;" : "=r"(a), "=r"(b) : "l"(v));
    lo = __uint_as_float(a);
    hi = __uint_as_float(b);
}

// ---------------- K1: h = feat @ W (FFMA2), 4 nodes x 16 outs / thread ----
// Block: 256 threads, 256 nodes. Thread (g = tid&63, q = tid>>6) computes
// nodes {base+g+64i, i<4} x outputs [16q,16q+16). acc = 32 u64 (64 regs)
// -> ~2 blocks/SM = 16 warps/SM, 8x the latency hiding of the R6 config.
__global__ __launch_bounds__(256) void gemm_kernel(
    const float* __restrict__ feat, const float* __restrict__ W,
    const float* __restrict__ attL, const float* __restrict__ attR) {
    __shared__ u64   sW2[INF * 32];          // 32 KB: rows of 64 f32 as 32 u64
    __shared__ float sF[8][GB_NODES];        // 8 KB: feat chunk [k][node]
    __shared__ float sAL[HF], sAR[HF];

    {
        const float2* ws = reinterpret_cast<const float2*>(W);
        float2* sd = reinterpret_cast<float2*>(sW2);
        for (int i = threadIdx.x; i < INF * 32; i += 256) sd[i] = ws[i];
        if (threadIdx.x < HF) {
            sAL[threadIdx.x] = attL[threadIdx.x];
            sAR[threadIdx.x] = attR[threadIdx.x];
        }
    }

    int tid = threadIdx.x;
    int g = tid & 63, q = tid >> 6;          // q uniform per warp -> W bcast
    int base = blockIdx.x * GB_NODES;

    u64 acc[32];
#pragma unroll
    for (int j = 0; j < 32; j++) acc[j] = 0ull;

    int ln = base + tid;                     // loader node (1 per thread)
    const float4 z4 = make_float4(0.f, 0.f, 0.f, 0.f);
    __syncthreads();

    for (int kc = 0; kc < 16; kc++) {
        int ks = kc * 8;
        float4 A0 = z4, A1 = z4;
        if (ln < NNODES) {
            const float4* p = reinterpret_cast<const float4*>(feat + (size_t)ln * INF + ks);
            A0 = p[0]; A1 = p[1];
        }
        __syncthreads();   // protect sF from previous iteration's readers
        sF[0][tid] = A0.x; sF[1][tid] = A0.y;
        sF[2][tid] = A0.z; sF[3][tid] = A0.w;
        sF[4][tid] = A1.x; sF[5][tid] = A1.y;
        sF[6][tid] = A1.z; sF[7][tid] = A1.w;
        __syncthreads();

#pragma unroll
        for (int k = 0; k < 8; k++) {
            const u64* wr = sW2 + (size_t)(ks + k) * 32 + q * 8;
            u64 w0 = wr[0], w1 = wr[1], w2 = wr[2], w3 = wr[3];
            u64 w4 = wr[4], w5 = wr[5], w6 = wr[6], w7 = wr[7];
#pragma unroll
            for (int i = 0; i < 4; i++) {
                u64 ai = bcast2(sF[k][g + 64 * i]);
                u64* a = acc + i * 8;
                a[0] = ffma2(ai, w0, a[0]);
                a[1] = ffma2(ai, w1, a[1]);
                a[2] = ffma2(ai, w2, a[2]);
                a[3] = ffma2(ai, w3, a[3]);
                a[4] = ffma2(ai, w4, a[4]);
                a[5] = ffma2(ai, w5, a[5]);
                a[6] = ffma2(ai, w6, a[6]);
                a[7] = ffma2(ai, w7, a[7]);
            }
        }
    }

    // epilogue: store h (fp16) + per-head el/er (no cross-thread reduction)
#pragma unroll
    for (int i = 0; i < 4; i++) {
        int n = base + g + 64 * i;
        if (n >= NNODES) continue;
        __half2* hr = reinterpret_cast<__half2*>(g_hh + (size_t)n * HF) + q * 8;
        float elv = 0.f, erv = 0.f;
#pragma unroll
        for (int j = 0; j < 8; j++) {
            float lo, hi;
            unpack2(acc[i * 8 + j], lo, hi);
            hr[j] = __floats2half2_rn(lo, hi);
            int j0 = q * 16 + 2 * j;
            elv = fmaf(lo, sAL[j0], fmaf(hi, sAL[j0 + 1], elv));
            erv = fmaf(lo, sAR[j0], fmaf(hi, sAR[j0 + 1], erv));
        }
        reinterpret_cast<float*>(g_el)[n * 4 + q] = elv;
        reinterpret_cast<float*>(g_er)[n * 4 + q] = erv;
    }
}

// ---------------- K2: target-degree histogram (4 edges/thread) ------------
__global__ void count_kernel(const int* __restrict__ trg) {
    int e4 = blockIdx.x * blockDim.x + threadIdx.x;
    if (e4 >= NEDGES / 4) return;
    int4 t = reinterpret_cast<const int4*>(trg)[e4];
    atomicAdd(&g_counts[t.x], 1);
    atomicAdd(&g_counts[t.y], 1);
    atomicAdd(&g_counts[t.z], 1);
    atomicAdd(&g_counts[t.w], 1);
}

// ---------------- K3: decoupled lookback scan, warp-parallel window -------
// Also re-zeroes g_counts after consuming (state recycling for next call).
__global__ __launch_bounds__(SBLK) void scan_kernel() {
    int b = blockIdx.x, tid = threadIdx.x;
    int lane = tid & 31, wid = tid >> 5;
    int i = b * SBLK + tid;
    int v = (i < NNODES) ? g_counts[i] : 0;

    // inclusive warp scan
    int x = v;
#pragma unroll
    for (int off = 1; off < 32; off <<= 1) {
        int u = __shfl_up_sync(0xFFFFFFFFu, x, off);
        if (lane >= off) x += u;
    }
    __shared__ int wsum[8], woff[8];
    __shared__ int s_prev;
    if (lane == 31) wsum[wid] = x;
    __syncthreads();

    if (tid < 32) {
        // scan the 8 warp sums in lanes 0..7
        int t = (lane < 8) ? wsum[lane] : 0;
        int s = t;
#pragma unroll
        for (int off = 1; off < 8; off <<= 1) {
            int u = __shfl_up_sync(0xFFFFFFFFu, s, off);
            if (lane >= off && lane < 8) s += u;
        }
        if (lane < 8) woff[lane] = s - t;
        int total = __shfl_sync(0xFFFFFFFFu, s, 7);

        if (b == 0) {
            if (lane == 0) {
                atomicExch(&g_state[0], ((u64)total << 2) | 2ull);
                s_prev = 0;
            }
        } else {
            if (lane == 0)
                atomicExch(&g_state[b], ((u64)total << 2) | 1ull);
            long long prev = 0;
            int look = b - 1;
            while (true) {
                int idx = look - lane;               // lane 0 = nearest pred
                u64 st = (idx >= 0) ? atomicAdd(&g_state[idx], 0ull) : 0ull;
                u64 fl = (idx >= 0) ? (st & 3ull) : 2ull;
                unsigned ready = __ballot_sync(0xFFFFFFFFu, fl != 0ull);
                if (ready != 0xFFFFFFFFu) { __nanosleep(20); continue; }
                unsigned pmask = __ballot_sync(0xFFFFFFFFu, fl == 2ull);
                int firstP = __ffs(pmask) - 1;       // -1 if all aggregates
                long long contrib =
                    (firstP < 0 || lane <= firstP) ? (long long)(st >> 2) : 0ll;
#pragma unroll
                for (int off = 16; off > 0; off >>= 1)
                    contrib += __shfl_down_sync(0xFFFFFFFFu, contrib, off);
                contrib = __shfl_sync(0xFFFFFFFFu, contrib, 0);
                prev += contrib;
                if (firstP >= 0) break;
                look -= 32;
            }
            if (lane == 0) {
                atomicExch(&g_state[b], ((u64)(prev + total) << 2) | 2ull);
                s_prev = (int)prev;
            }
        }
    }
    __syncthreads();
    if (i < NNODES) {
        int pos = s_prev + woff[wid] + x - v;  // global exclusive prefix
        g_rowptr[i] = pos;
        g_cursor[i] = pos;
        g_counts[i] = 0;                       // recycle for next call
        if (i == NNODES - 1) g_rowptr[NNODES] = NEDGES;
    }
}

// ---------------- K4: scatter src ids; also recycle lookback state --------
__global__ void scatter_kernel(const int* __restrict__ src,
                               const int* __restrict__ trg) {
    int e4 = blockIdx.x * blockDim.x + threadIdx.x;
    if (e4 < NSB) g_state[e4] = 0ull;          // reset for next call
    if (e4 >= NEDGES / 4) return;
    int4 t = reinterpret_cast<const int4*>(trg)[e4];
    int4 s = reinterpret_cast<const int4*>(src)[e4];
    g_psrc[atomicAdd(&g_cursor[t.x], 1)] = s.x;
    g_psrc[atomicAdd(&g_cursor[t.y], 1)] = s.y;
    g_psrc[atomicAdd(&g_cursor[t.z], 1)] = s.z;
    g_psrc[atomicAdd(&g_cursor[t.w], 1)] = s.w;
}

// ---------------- K5: single-pass warp-per-node softmax + aggregation -----
// Unnormalized accumulate Sum(e_i * h_i); divide by Sum(e_i)+EPS at the end.
// Inner loop: 4 edges x 16B per iteration (jsub = lane>>3, chunk c = lane&7),
// then combine partials across jsub groups with shfl-xor.
__global__ __launch_bounds__(256) void agg_kernel(float* __restrict__ out) {
    __shared__ int   s_src[8][32];
    __shared__ float s_exp[8][32 * 4];

    int gw = (blockIdx.x * 256 + threadIdx.x) >> 5;   // node
    int lane = threadIdx.x & 31;
    int ws = (threadIdx.x >> 5);
    if (gw >= NNODES) return;

    int beg = g_rowptr[gw];
    int end = g_rowptr[gw + 1];
    float4 er = g_er[gw];
    int c = lane & 7;            // feature chunk: halfs [8c, 8c+8)
    int jsub = lane >> 3;        // edge sub-index within group of 4
    int head = c >> 1;           // head of this feature chunk

    float acc[8];
#pragma unroll
    for (int k = 0; k < 8; k++) acc[k] = 0.f;
    float4 dp = make_float4(0.f, 0.f, 0.f, 0.f);   // per-lane denom partials
    const char* hb = reinterpret_cast<const char*>(g_hh);

    for (int t0 = beg; t0 < end; t0 += 32) {
        int cnt = min(32, end - t0);
        int s = 0;
        float4 e4 = make_float4(0.f, 0.f, 0.f, 0.f);
        if (lane < cnt) {
            s = __ldg(&g_psrc[t0 + lane]);          // sequential coalesced
            float4 l = g_el[s];                     // 16B gather, L2-resident
            float sx = l.x + er.x, sy = l.y + er.y;
            float sz = l.z + er.z, sw = l.w + er.w;
            sx = sx > 0.f ? sx : NEG_SLOPE * sx;
            sy = sy > 0.f ? sy : NEG_SLOPE * sy;
            sz = sz > 0.f ? sz : NEG_SLOPE * sz;
            sw = sw > 0.f ? sw : NEG_SLOPE * sw;
            e4 = make_float4(__expf(sx), __expf(sy), __expf(sz), __expf(sw));
            dp.x += e4.x; dp.y += e4.y; dp.z += e4.z; dp.w += e4.w;
        }
        s_src[ws][lane] = s;                        // inactive lanes: 0, a=0
        reinterpret_cast<float4*>(s_exp[ws])[lane] = e4;
        __syncwarp();

        int nIter = (cnt + 3) >> 2;
#pragma unroll 2
        for (int j4 = 0; j4 < nIter; j4++) {
            int j = j4 * 4 + jsub;                  // j <= 31 always
            int sj = s_src[ws][j];
            float a = s_exp[ws][j * 4 + head];
            uint4 hv = *reinterpret_cast<const uint4*>(
                hb + (size_t)sj * 128 + c * 16);
            float2 f0 = __half22float2(*reinterpret_cast<__half2*>(&hv.x));
            float2 f1 = __half22float2(*reinterpret_cast<__half2*>(&hv.y));
            float2 f2 = __half22float2(*reinterpret_cast<__half2*>(&hv.z));
            float2 f3 = __half22float2(*reinterpret_cast<__half2*>(&hv.w));
            acc[0] = fmaf(f0.x, a, acc[0]);
            acc[1] = fmaf(f0.y, a, acc[1]);
            acc[2] = fmaf(f1.x, a, acc[2]);
            acc[3] = fmaf(f1.y, a, acc[3]);
            acc[4] = fmaf(f2.x, a, acc[4]);
            acc[5] = fmaf(f2.y, a, acc[5]);
            acc[6] = fmaf(f3.x, a, acc[6]);
            acc[7] = fmaf(f3.y, a, acc[7]);
        }
        __syncwarp();
    }

    // combine partial sums across the 4 jsub groups (lanes xor 8, 16)
#pragma unroll
    for (int k = 0; k < 8; k++) {
        acc[k] += __shfl_xor_sync(0xFFFFFFFFu, acc[k], 8);
        acc[k] += __shfl_xor_sync(0xFFFFFFFFu, acc[k], 16);
    }

    // reduce denom partials across all lanes
#pragma unroll
    for (int off = 16; off > 0; off >>= 1) {
        dp.x += __shfl_xor_sync(0xFFFFFFFFu, dp.x, off);
        dp.y += __shfl_xor_sync(0xFFFFFFFFu, dp.y, off);
        dp.z += __shfl_xor_sync(0xFFFFFFFFu, dp.z, off);
        dp.w += __shfl_xor_sync(0xFFFFFFFFu, dp.w, off);
    }
    float denom = (head == 0) ? dp.x : (head == 1) ? dp.y
                : (head == 2) ? dp.z : dp.w;
    float rd = 1.0f / (denom + EPS_F);

    if (jsub == 0) {                               // lanes 0..7 write the row
        float4* orow = reinterpret_cast<float4*>(out + (size_t)gw * HF + c * 8);
        orow[0] = make_float4(acc[0] * rd, acc[1] * rd, acc[2] * rd, acc[3] * rd);
        orow[1] = make_float4(acc[4] * rd, acc[5] * rd, acc[6] * rd, acc[7] * rd);
    }
}

// ---------------- launch ---------------------------------------------------
extern "C" void kernel_launch(void* const* d_in, const int* in_sizes, int n_in,
                              void* d_out, int out_size) {
    const float* feat = (const float*)d_in[0];
    const float* W    = (const float*)d_in[1];
    const float* attL = (const float*)d_in[2];
    const float* attR = (const float*)d_in[3];
    const int*   src  = (const int*)d_in[4];
    const int*   trg  = (const int*)d_in[5];
    float* out = (float*)d_out;

    // side stream + events, created once on the (uncaptured) correctness call
    static cudaStream_t s2 = 0;
    static cudaEvent_t  e0 = 0, e1 = 0;
    static bool ready = false;
    if (!ready) {
        bool ok = (cudaStreamCreateWithFlags(&s2, cudaStreamNonBlocking) == cudaSuccess)
               && (cudaEventCreateWithFlags(&e0, cudaEventDisableTiming) == cudaSuccess)
               && (cudaEventCreateWithFlags(&e1, cudaEventDisableTiming) == cudaSuccess);
        if (!ok) { s2 = 0; e0 = e1 = 0; }
        ready = true;
    }

    bool fork = (s2 != 0);
    if (fork) {
        cudaEventRecord(e0, 0);
        cudaStreamWaitEvent(s2, e0, 0);
    }
    // branch A (side stream): projection GEMM (independent of CSR build)
    gemm_kernel<<<NGB, 256, 0, fork ? s2 : 0>>>(feat, W, attL, attR);
    if (fork) cudaEventRecord(e1, s2);

    // branch B (legacy stream): CSR build
    count_kernel<<<(NEDGES / 4 + 255) / 256, 256>>>(trg);
    scan_kernel<<<NSB, SBLK>>>();
    scatter_kernel<<<(NEDGES / 4 + 255) / 256, 256>>>(src, trg);

    // join, then aggregate
    if (fork) cudaStreamWaitEvent(0, e1, 0);
    agg_kernel<<<(NNODES * 32 + 255) / 256, 256>>>(out);
}

// round 9
// speedup vs baseline: 1.0031x; 1.0031x over previous
#include <cuda_runtime.h>
#include <cuda_fp16.h>
#include <cuda_bf16.h>

#define NNODES 100000
#define NEDGES 1600000
#define INF    128
#define HF     64     // HEADS*OUT_FEATS
#define NEG_SLOPE 0.2f
#define EPS_F  1e-16f

#define GB_NODES 256                         // nodes per gemm block
#define NGB ((NNODES + GB_NODES - 1) / GB_NODES)   // 391 gemm blocks
#define SBLK 256
#define NSB  ((NNODES + SBLK - 1) / SBLK)    // 391 scan blocks

typedef unsigned long long u64;

// ---------------- static device scratch (no allocations allowed) ----------
// State-recycling invariant: g_counts and g_state are all-zero on entry to
// every kernel_launch call (BSS-zero initially; scan re-zeroes counts after
// consuming them, scatter re-zeroes the lookback states after scan).
__device__ __half g_hh[NNODES * HF];         // 12.8 MB projected features (fp16)
__device__ float4 g_el[NNODES];              // [N][4] left scores
__device__ float4 g_er[NNODES];              // [N][4] right scores
__device__ int    g_counts[NNODES];
__device__ int    g_cursor[NNODES];
__device__ int    g_rowptr[NNODES + 1];
__device__ int    g_psrc[NEDGES];            // src ids grouped by target
__device__ u64    g_state[NSB];              // lookback: (sum<<2)|{0,1,2}

// ---------------- packed f32x2 helpers (sm_103a FFMA2) --------------------
__device__ __forceinline__ u64 ffma2(u64 a, u64 b, u64 c) {
    u64 d;
    asm("fma.rn.f32x2 %0, %1, %2, %3;" : "=l"(d) : "l"(a), "l"(b), "l"(c));
    return d;
}
__device__ __forceinline__ u64 bcast2(float x) {
    u64 d;
    unsigned u = __float_as_uint(x);
    asm("mov.b64 %0, {%1, %1};" : "=l"(d) : "r"(u));
    return d;
}
__device__ __forceinline__ void unpack2(u64 v, float& lo, float& hi) {
    unsigned a, b;
    asm("mov.b64 {%0, %1}, %2;" : "=r"(a), "=r"(b) : "l"(v));
    lo = __uint_as_float(a);
    hi = __uint_as_float(b);
}

// ---------------- K1: h = feat @ W (FFMA2), tiled (R7 config) -------------
// Block: 128 threads, 256 nodes. Thread (g = tid&31, q = tid>>5) computes
// 8 nodes {base+g+32i} x 16 outputs (head q). W broadcast from smem,
// feat staged per-block in smem.
__global__ __launch_bounds__(128, 2) void gemm_kernel(
    const float* __restrict__ feat, const float* __restrict__ W,
    const float* __restrict__ attL, const float* __restrict__ attR) {
    __shared__ u64   sW2[INF * 32];          // 32 KB: rows of 64 f32 as 32 u64
    __shared__ float sF[8][GB_NODES];        // 8 KB: feat chunk [k][node]
    __shared__ float sAL[HF], sAR[HF];

    {
        const float2* ws = reinterpret_cast<const float2*>(W);
        float2* sd = reinterpret_cast<float2*>(sW2);
        for (int i = threadIdx.x; i < INF * 32; i += 128) sd[i] = ws[i];
        if (threadIdx.x < HF) {
            sAL[threadIdx.x] = attL[threadIdx.x];
            sAR[threadIdx.x] = attR[threadIdx.x];
        }
    }

    int tid = threadIdx.x;
    int g = tid & 31, q = tid >> 5;
    int base = blockIdx.x * GB_NODES;

    u64 acc[64];
#pragma unroll
    for (int j = 0; j < 64; j++) acc[j] = 0ull;

    int ln0 = base + 2 * tid;                // loader nodes
    int ln1 = ln0 + 1;
    const float4 z4 = make_float4(0.f, 0.f, 0.f, 0.f);
    __syncthreads();

    for (int kc = 0; kc < 16; kc++) {
        int ks = kc * 8;
        float4 A0 = z4, A1 = z4, B0 = z4, B1 = z4;
        if (ln0 < NNODES) {
            const float4* p = reinterpret_cast<const float4*>(feat + (size_t)ln0 * INF + ks);
            A0 = p[0]; A1 = p[1];
        }
        if (ln1 < NNODES) {
            const float4* p = reinterpret_cast<const float4*>(feat + (size_t)ln1 * INF + ks);
            B0 = p[0]; B1 = p[1];
        }
        __syncthreads();   // protect sF from previous iteration's readers
        float2* row;
        row = reinterpret_cast<float2*>(&sF[0][2 * tid]); *row = make_float2(A0.x, B0.x);
        row = reinterpret_cast<float2*>(&sF[1][2 * tid]); *row = make_float2(A0.y, B0.y);
        row = reinterpret_cast<float2*>(&sF[2][2 * tid]); *row = make_float2(A0.z, B0.z);
        row = reinterpret_cast<float2*>(&sF[3][2 * tid]); *row = make_float2(A0.w, B0.w);
        row = reinterpret_cast<float2*>(&sF[4][2 * tid]); *row = make_float2(A1.x, B1.x);
        row = reinterpret_cast<float2*>(&sF[5][2 * tid]); *row = make_float2(A1.y, B1.y);
        row = reinterpret_cast<float2*>(&sF[6][2 * tid]); *row = make_float2(A1.z, B1.z);
        row = reinterpret_cast<float2*>(&sF[7][2 * tid]); *row = make_float2(A1.w, B1.w);
        __syncthreads();

#pragma unroll
        for (int k = 0; k < 8; k++) {
            const u64* wr = sW2 + (size_t)(ks + k) * 32 + q * 8;
            u64 w0 = wr[0], w1 = wr[1], w2 = wr[2], w3 = wr[3];
            u64 w4 = wr[4], w5 = wr[5], w6 = wr[6], w7 = wr[7];
#pragma unroll
            for (int i = 0; i < 8; i++) {
                u64 ai = bcast2(sF[k][g + 32 * i]);
                u64* a = acc + i * 8;
                a[0] = ffma2(ai, w0, a[0]);
                a[1] = ffma2(ai, w1, a[1]);
                a[2] = ffma2(ai, w2, a[2]);
                a[3] = ffma2(ai, w3, a[3]);
                a[4] = ffma2(ai, w4, a[4]);
                a[5] = ffma2(ai, w5, a[5]);
                a[6] = ffma2(ai, w6, a[6]);
                a[7] = ffma2(ai, w7, a[7]);
            }
        }
    }

    // epilogue: store h (fp16) + per-head el/er (no cross-thread reduction)
#pragma unroll
    for (int i = 0; i < 8; i++) {
        int n = base + g + 32 * i;
        if (n >= NNODES) continue;
        __half2* hr = reinterpret_cast<__half2*>(g_hh + (size_t)n * HF) + q * 8;
        float elv = 0.f, erv = 0.f;
#pragma unroll
        for (int j = 0; j < 8; j++) {
            float lo, hi;
            unpack2(acc[i * 8 + j], lo, hi);
            hr[j] = __floats2half2_rn(lo, hi);
            int j0 = q * 16 + 2 * j;
            elv = fmaf(lo, sAL[j0], fmaf(hi, sAL[j0 + 1], elv));
            erv = fmaf(lo, sAR[j0], fmaf(hi, sAR[j0 + 1], erv));
        }
        reinterpret_cast<float*>(g_el)[n * 4 + q] = elv;
        reinterpret_cast<float*>(g_er)[n * 4 + q] = erv;
    }
}

// ---------------- K2: target-degree histogram (8 edges/thread) ------------
__global__ void count_kernel(const int* __restrict__ trg) {
    int e8 = blockIdx.x * blockDim.x + threadIdx.x;
    if (e8 >= NEDGES / 8) return;
    int4 t0 = reinterpret_cast<const int4*>(trg)[e8 * 2];
    int4 t1 = reinterpret_cast<const int4*>(trg)[e8 * 2 + 1];
    atomicAdd(&g_counts[t0.x], 1);
    atomicAdd(&g_counts[t0.y], 1);
    atomicAdd(&g_counts[t0.z], 1);
    atomicAdd(&g_counts[t0.w], 1);
    atomicAdd(&g_counts[t1.x], 1);
    atomicAdd(&g_counts[t1.y], 1);
    atomicAdd(&g_counts[t1.z], 1);
    atomicAdd(&g_counts[t1.w], 1);
}

// ---------------- K3: decoupled lookback scan, warp-parallel window -------
// Also re-zeroes g_counts after consuming (state recycling for next call).
__global__ __launch_bounds__(SBLK) void scan_kernel() {
    int b = blockIdx.x, tid = threadIdx.x;
    int lane = tid & 31, wid = tid >> 5;
    int i = b * SBLK + tid;
    int v = (i < NNODES) ? g_counts[i] : 0;

    // inclusive warp scan
    int x = v;
#pragma unroll
    for (int off = 1; off < 32; off <<= 1) {
        int u = __shfl_up_sync(0xFFFFFFFFu, x, off);
        if (lane >= off) x += u;
    }
    __shared__ int wsum[8], woff[8];
    __shared__ int s_prev;
    if (lane == 31) wsum[wid] = x;
    __syncthreads();

    if (tid < 32) {
        // scan the 8 warp sums in lanes 0..7
        int t = (lane < 8) ? wsum[lane] : 0;
        int s = t;
#pragma unroll
        for (int off = 1; off < 8; off <<= 1) {
            int u = __shfl_up_sync(0xFFFFFFFFu, s, off);
            if (lane >= off && lane < 8) s += u;
        }
        if (lane < 8) woff[lane] = s - t;
        int total = __shfl_sync(0xFFFFFFFFu, s, 7);

        if (b == 0) {
            if (lane == 0) {
                atomicExch(&g_state[0], ((u64)total << 2) | 2ull);
                s_prev = 0;
            }
        } else {
            if (lane == 0)
                atomicExch(&g_state[b], ((u64)total << 2) | 1ull);
            long long prev = 0;
            int look = b - 1;
            while (true) {
                int idx = look - lane;               // lane 0 = nearest pred
                u64 st = (idx >= 0) ? atomicAdd(&g_state[idx], 0ull) : 0ull;
                u64 fl = (idx >= 0) ? (st & 3ull) : 2ull;
                unsigned ready = __ballot_sync(0xFFFFFFFFu, fl != 0ull);
                if (ready != 0xFFFFFFFFu) { __nanosleep(20); continue; }
                unsigned pmask = __ballot_sync(0xFFFFFFFFu, fl == 2ull);
                int firstP = __ffs(pmask) - 1;       // -1 if all aggregates
                long long contrib =
                    (firstP < 0 || lane <= firstP) ? (long long)(st >> 2) : 0ll;
#pragma unroll
                for (int off = 16; off > 0; off >>= 1)
                    contrib += __shfl_down_sync(0xFFFFFFFFu, contrib, off);
                contrib = __shfl_sync(0xFFFFFFFFu, contrib, 0);
                prev += contrib;
                if (firstP >= 0) break;
                look -= 32;
            }
            if (lane == 0) {
                atomicExch(&g_state[b], ((u64)(prev + total) << 2) | 2ull);
                s_prev = (int)prev;
            }
        }
    }
    __syncthreads();
    if (i < NNODES) {
        int pos = s_prev + woff[wid] + x - v;  // global exclusive prefix
        g_rowptr[i] = pos;
        g_cursor[i] = pos;
        g_counts[i] = 0;                       // recycle for next call
        if (i == NNODES - 1) g_rowptr[NNODES] = NEDGES;
    }
}

// ---------------- K4: scatter src ids (8 edges/thread, high MLP) ----------
// Also recycles lookback state for the next call.
__global__ void scatter_kernel(const int* __restrict__ src,
                               const int* __restrict__ trg) {
    int e8 = blockIdx.x * blockDim.x + threadIdx.x;
    if (e8 < NSB) g_state[e8] = 0ull;          // reset for next call
    if (e8 >= NEDGES / 8) return;
    int4 t0 = reinterpret_cast<const int4*>(trg)[e8 * 2];
    int4 t1 = reinterpret_cast<const int4*>(trg)[e8 * 2 + 1];
    int4 s0 = reinterpret_cast<const int4*>(src)[e8 * 2];
    int4 s1 = reinterpret_cast<const int4*>(src)[e8 * 2 + 1];
    int p0 = atomicAdd(&g_cursor[t0.x], 1);
    int p1 = atomicAdd(&g_cursor[t0.y], 1);
    int p2 = atomicAdd(&g_cursor[t0.z], 1);
    int p3 = atomicAdd(&g_cursor[t0.w], 1);
    int p4 = atomicAdd(&g_cursor[t1.x], 1);
    int p5 = atomicAdd(&g_cursor[t1.y], 1);
    int p6 = atomicAdd(&g_cursor[t1.z], 1);
    int p7 = atomicAdd(&g_cursor[t1.w], 1);
    g_psrc[p0] = s0.x;
    g_psrc[p1] = s0.y;
    g_psrc[p2] = s0.z;
    g_psrc[p3] = s0.w;
    g_psrc[p4] = s1.x;
    g_psrc[p5] = s1.y;
    g_psrc[p6] = s1.z;
    g_psrc[p7] = s1.w;
}

// ---------------- K5: single-pass warp-per-node softmax + aggregation -----
// Unnormalized accumulate Sum(e_i * h_i); divide by Sum(e_i)+EPS at the end.
// Inner loop: 4 edges x 16B per iteration (jsub = lane>>3, chunk c = lane&7),
// then combine partials across jsub groups with shfl-xor.
__global__ __launch_bounds__(256) void agg_kernel(float* __restrict__ out) {
    __shared__ int   s_src[8][32];
    __shared__ float s_exp[8][32 * 4];

    int gw = (blockIdx.x * 256 + threadIdx.x) >> 5;   // node
    int lane = threadIdx.x & 31;
    int ws = (threadIdx.x >> 5);
    if (gw >= NNODES) return;

    int beg = g_rowptr[gw];
    int end = g_rowptr[gw + 1];
    float4 er = g_er[gw];
    int c = lane & 7;            // feature chunk: halfs [8c, 8c+8)
    int jsub = lane >> 3;        // edge sub-index within group of 4
    int head = c >> 1;           // head of this feature chunk

    float acc[8];
#pragma unroll
    for (int k = 0; k < 8; k++) acc[k] = 0.f;
    float4 dp = make_float4(0.f, 0.f, 0.f, 0.f);   // per-lane denom partials
    const char* hb = reinterpret_cast<const char*>(g_hh);

    for (int t0 = beg; t0 < end; t0 += 32) {
        int cnt = min(32, end - t0);
        int s = 0;
        float4 e4 = make_float4(0.f, 0.f, 0.f, 0.f);
        if (lane < cnt) {
            s = __ldg(&g_psrc[t0 + lane]);          // sequential coalesced
            float4 l = g_el[s];                     // 16B gather, L2-resident
            float sx = l.x + er.x, sy = l.y + er.y;
            float sz = l.z + er.z, sw = l.w + er.w;
            sx = sx > 0.f ? sx : NEG_SLOPE * sx;
            sy = sy > 0.f ? sy : NEG_SLOPE * sy;
            sz = sz > 0.f ? sz : NEG_SLOPE * sz;
            sw = sw > 0.f ? sw : NEG_SLOPE * sw;
            e4 = make_float4(__expf(sx), __expf(sy), __expf(sz), __expf(sw));
            dp.x += e4.x; dp.y += e4.y; dp.z += e4.z; dp.w += e4.w;
        }
        s_src[ws][lane] = s;                        // inactive lanes: 0, a=0
        reinterpret_cast<float4*>(s_exp[ws])[lane] = e4;
        __syncwarp();

        int nIter = (cnt + 3) >> 2;
#pragma unroll 2
        for (int j4 = 0; j4 < nIter; j4++) {
            int j = j4 * 4 + jsub;                  // j <= 31 always
            int sj = s_src[ws][j];
            float a = s_exp[ws][j * 4 + head];
            uint4 hv = *reinterpret_cast<const uint4*>(
                hb + (size_t)sj * 128 + c * 16);
            float2 f0 = __half22float2(*reinterpret_cast<__half2*>(&hv.x));
            float2 f1 = __half22float2(*reinterpret_cast<__half2*>(&hv.y));
            float2 f2 = __half22float2(*reinterpret_cast<__half2*>(&hv.z));
            float2 f3 = __half22float2(*reinterpret_cast<__half2*>(&hv.w));
            acc[0] = fmaf(f0.x, a, acc[0]);
            acc[1] = fmaf(f0.y, a, acc[1]);
            acc[2] = fmaf(f1.x, a, acc[2]);
            acc[3] = fmaf(f1.y, a, acc[3]);
            acc[4] = fmaf(f2.x, a, acc[4]);
            acc[5] = fmaf(f2.y, a, acc[5]);
            acc[6] = fmaf(f3.x, a, acc[6]);
            acc[7] = fmaf(f3.y, a, acc[7]);
        }
        __syncwarp();
    }

    // combine partial sums across the 4 jsub groups (lanes xor 8, 16)
#pragma unroll
    for (int k = 0; k < 8; k++) {
        acc[k] += __shfl_xor_sync(0xFFFFFFFFu, acc[k], 8);
        acc[k] += __shfl_xor_sync(0xFFFFFFFFu, acc[k], 16);
    }

    // reduce denom partials across all lanes
#pragma unroll
    for (int off = 16; off > 0; off >>= 1) {
        dp.x += __shfl_xor_sync(0xFFFFFFFFu, dp.x, off);
        dp.y += __shfl_xor_sync(0xFFFFFFFFu, dp.y, off);
        dp.z += __shfl_xor_sync(0xFFFFFFFFu, dp.z, off);
        dp.w += __shfl_xor_sync(0xFFFFFFFFu, dp.w, off);
    }
    float denom = (head == 0) ? dp.x : (head == 1) ? dp.y
                : (head == 2) ? dp.z : dp.w;
    float rd = 1.0f / (denom + EPS_F);

    if (jsub == 0) {                               // lanes 0..7 write the row
        float4* orow = reinterpret_cast<float4*>(out + (size_t)gw * HF + c * 8);
        orow[0] = make_float4(acc[0] * rd, acc[1] * rd, acc[2] * rd, acc[3] * rd);
        orow[1] = make_float4(acc[4] * rd, acc[5] * rd, acc[6] * rd, acc[7] * rd);
    }
}

// ---------------- launch ---------------------------------------------------
extern "C" void kernel_launch(void* const* d_in, const int* in_sizes, int n_in,
                              void* d_out, int out_size) {
    const float* feat = (const float*)d_in[0];
    const float* W    = (const float*)d_in[1];
    const float* attL = (const float*)d_in[2];
    const float* attR = (const float*)d_in[3];
    const int*   src  = (const int*)d_in[4];
    const int*   trg  = (const int*)d_in[5];
    float* out = (float*)d_out;

    // side stream + events, created once on the (uncaptured) correctness call
    static cudaStream_t s2 = 0;
    static cudaEvent_t  e0 = 0, e1 = 0;
    static bool ready = false;
    if (!ready) {
        bool ok = (cudaStreamCreateWithFlags(&s2, cudaStreamNonBlocking) == cudaSuccess)
               && (cudaEventCreateWithFlags(&e0, cudaEventDisableTiming) == cudaSuccess)
               && (cudaEventCreateWithFlags(&e1, cudaEventDisableTiming) == cudaSuccess);
        if (!ok) { s2 = 0; e0 = e1 = 0; }
        ready = true;
    }

    bool fork = (s2 != 0);
    if (fork) {
        cudaEventRecord(e0, 0);
        cudaStreamWaitEvent(s2, e0, 0);
    }

    // branch B (legacy stream): CSR build — launched first so gemm is the
    // 4th kernel launch (ncu -s 5 -c 1 lands on it; still overlaps via s2).
    count_kernel<<<(NEDGES / 8 + 255) / 256, 256>>>(trg);
    scan_kernel<<<NSB, SBLK>>>();
    scatter_kernel<<<(NEDGES / 8 + 255) / 256, 256>>>(src, trg);

    // branch A (side stream): projection GEMM (independent of CSR build)
    gemm_kernel<<<NGB, 128, 0, fork ? s2 : 0>>>(feat, W, attL, attR);
    if (fork) cudaEventRecord(e1, s2);

    // join, then aggregate
    if (fork) cudaStreamWaitEvent(0, e1, 0);
    agg_kernel<<<(NNODES * 32 + 255) / 256, 256>>>(out);
}